// round 16
// baseline (speedup 1.0000x reference)
#include <cuda_runtime.h>
#include <cstdint>

// MultiDirectionPattern: masked 8-direction pooling + saliency gather.
// Champion + L2::evict_first on BOTH read-once streams:
//  - x tile cp.async.bulk (confirmed 20.99us in R15)
//  - sal-path gathered s reads (same mechanism: read-once, dead after use)
// Hot data (fm, g_exp, sal_idx) keeps normal L2 caching.

static constexpr int HW    = 49;     // 7*7
static constexpr int TPB   = 64;
static constexpr int SROW  = 3136;   // 56*56
static constexpr int WROWS = 32;     // rows per warp
static constexpr int WF    = WROWS * HW;     // 1568 floats per warp slice
static constexpr int WBYTES = WF * 4;        // 6272 bytes
static constexpr int SM_FLOATS = 2 * WF;     // 3136 floats = 12544 B

// Expected mask values (1.0 where feat_mask[p][k] != 0): vectorized verify.
#define Z 0.f
#define O 1.f
__device__ const float g_exp[392] = {
// p0: 24,25,26,27,32,33,34,40,41,48
Z,Z,Z,Z,Z,Z,Z,Z,Z,Z,Z,Z,Z,Z,Z,Z,Z,Z,Z,Z,Z,Z,Z,Z,O,O,O,O,Z,Z,Z,Z,O,O,O,Z,Z,Z,Z,Z,O,O,Z,Z,Z,Z,Z,Z,O,
// p1: 24,31,32,38,39,40,45,46,47,48
Z,Z,Z,Z,Z,Z,Z,Z,Z,Z,Z,Z,Z,Z,Z,Z,Z,Z,Z,Z,Z,Z,Z,Z,O,Z,Z,Z,Z,Z,Z,O,O,Z,Z,Z,Z,Z,O,O,O,Z,Z,Z,Z,O,O,O,O,
// p2: 24,30,31,36,37,38,42,43,44,45
Z,Z,Z,Z,Z,Z,Z,Z,Z,Z,Z,Z,Z,Z,Z,Z,Z,Z,Z,Z,Z,Z,Z,Z,O,Z,Z,Z,Z,Z,O,O,Z,Z,Z,Z,O,O,O,Z,Z,Z,O,O,O,O,Z,Z,Z,
// p3: 21,22,23,24,28,29,30,35,36,42
Z,Z,Z,Z,Z,Z,Z,Z,Z,Z,Z,Z,Z,Z,Z,Z,Z,Z,Z,Z,Z,O,O,O,O,Z,Z,Z,O,O,O,Z,Z,Z,Z,O,O,Z,Z,Z,Z,Z,O,Z,Z,Z,Z,Z,Z,
// p4: 0,7,8,14,15,16,21,22,23,24
O,Z,Z,Z,Z,Z,Z,O,O,Z,Z,Z,Z,Z,O,O,O,Z,Z,Z,Z,O,O,O,O,Z,Z,Z,Z,Z,Z,Z,Z,Z,Z,Z,Z,Z,Z,Z,Z,Z,Z,Z,Z,Z,Z,Z,Z,
// p5: 0,1,2,3,8,9,10,16,17,24
O,O,O,O,Z,Z,Z,Z,O,O,O,Z,Z,Z,Z,Z,O,O,Z,Z,Z,Z,Z,Z,O,Z,Z,Z,Z,Z,Z,Z,Z,Z,Z,Z,Z,Z,Z,Z,Z,Z,Z,Z,Z,Z,Z,Z,Z,
// p6: 3,4,5,6,10,11,12,17,18,24
Z,Z,Z,O,O,O,O,Z,Z,Z,O,O,O,Z,Z,Z,Z,O,O,Z,Z,Z,Z,Z,O,Z,Z,Z,Z,Z,Z,Z,Z,Z,Z,Z,Z,Z,Z,Z,Z,Z,Z,Z,Z,Z,Z,Z,Z,
// p7: 6,12,13,18,19,20,24,25,26,27
Z,Z,Z,Z,Z,Z,O,Z,Z,Z,Z,Z,O,O,Z,Z,Z,Z,O,O,O,Z,Z,Z,O,O,O,O,Z,Z,Z,Z,Z,Z,Z,Z,Z,Z,Z,Z,Z,Z,Z,Z,Z,Z,Z,Z,Z
};
#undef Z
#undef O

__device__ __forceinline__ void cp16(uint32_t dst, const void* src) {
    asm volatile("cp.async.cg.shared.global [%0], [%1], 16;\n" :: "r"(dst), "l"(src));
}
__device__ __forceinline__ void cp4(uint32_t dst, const void* src) {
    asm volatile("cp.async.ca.shared.global [%0], [%1], 4;\n" :: "r"(dst), "l"(src));
}
__device__ __forceinline__ void cp_commit() {
    asm volatile("cp.async.commit_group;\n" ::: "memory");
}
__device__ __forceinline__ void cp_wait_all() {
    asm volatile("cp.async.wait_group 0;\n" ::: "memory");
}
__device__ __forceinline__ void mbar_init(uint32_t mbar, uint32_t cnt) {
    asm volatile("mbarrier.init.shared.b64 [%0], %1;\n" :: "r"(mbar), "r"(cnt) : "memory");
}
__device__ __forceinline__ void fence_async() {
    asm volatile("fence.proxy.async.shared::cta;\n" ::: "memory");
}
__device__ __forceinline__ void mbar_expect_tx(uint32_t mbar, uint32_t bytes) {
    asm volatile("mbarrier.arrive.expect_tx.shared.b64 _, [%0], %1;\n"
                 :: "r"(mbar), "r"(bytes) : "memory");
}
// bulk copy with L2 evict_first cache hint (x is read-once)
__device__ __forceinline__ void cp_bulk_ef(uint32_t dst, const void* src,
                                           uint32_t bytes, uint32_t mbar) {
    asm volatile(
        "{\n\t.reg .b64 pol;\n\t"
        "createpolicy.fractional.L2::evict_first.b64 pol, 1.0;\n\t"
        "cp.async.bulk.shared::cta.global.mbarrier::complete_tx::bytes.L2::cache_hint "
        "[%0], [%1], %2, [%3], pol;\n\t}"
        :: "r"(dst), "l"(src), "r"(bytes), "r"(mbar) : "memory");
}
// read-once scalar load with evict_first hint (sal-path s gathers)
__device__ __forceinline__ float ldg_ef(const float* p) {
    float v;
    asm volatile(
        "{\n\t.reg .b64 pol;\n\t"
        "createpolicy.fractional.L2::evict_first.b64 pol, 1.0;\n\t"
        "ld.global.nc.L2::cache_hint.f32 %0, [%1], pol;\n\t}"
        : "=f"(v) : "l"(p));
    return v;
}
__device__ __forceinline__ void mbar_wait(uint32_t mbar, uint32_t parity) {
    uint32_t done;
    asm volatile(
        "{\n\t.reg .pred p;\n\t"
        "mbarrier.try_wait.parity.acquire.cta.shared::cta.b64 p, [%1], %2;\n\t"
        "selp.b32 %0, 1, 0, p;\n\t}"
        : "=r"(done) : "r"(mbar), "r"(parity) : "memory");
    if (!done) {
        asm volatile(
            "{\n\t.reg .pred P1;\n\t"
            "WL_%=:\n\t"
            "mbarrier.try_wait.parity.acquire.cta.shared::cta.b64 P1, [%0], %1, 0x989680;\n\t"
            "@P1 bra.uni WD_%=;\n\t"
            "bra.uni WL_%=;\n\t"
            "WD_%=:\n\t}"
            :: "r"(mbar), "r"(parity) : "memory");
    }
}

__global__ __launch_bounds__(TPB, 17) void fused_kernel(
    const float* __restrict__ x,
    const float* __restrict__ s,
    const float* __restrict__ fm,
    const int*   __restrict__ sal_idx,
    float*       __restrict__ out,
    int rows,             // B*C
    int B,                // batch (sal blocks are blk < B)
    int N,                // saliency points per direction
    long long feat_elems  // rows*8
) {
    __shared__ __align__(16) float sm[SM_FLOATS];
    __shared__ __align__(8) unsigned long long smbar[2];
    const int blk = blockIdx.x;
    const int t   = threadIdx.x;

    if (blk >= B) {
        // ============ feat tile: warp-autonomous, 32 rows/warp ============
        const uint32_t sbase = (uint32_t)__cvta_generic_to_shared(sm);
        const uint32_t mbase = (uint32_t)__cvta_generic_to_shared(smbar);
        const int w    = t >> 5;
        const int lane = t & 31;
        const long long wrow0 = (long long)(blk - B) * TPB + (long long)w * WROWS;
        long long rem = rows - wrow0;
        if (rem <= 0) return;                    // no barriers in this path
        const int rh = rem < WROWS ? (int)rem : WROWS;

        float* wbuf = sm + w * WF;
        const uint32_t dst  = sbase + (uint32_t)w * WBYTES;
        const uint32_t mbar = mbase + (uint32_t)w * 8;
        const float* xw = x + wrow0 * HW;        // wrow0 mult of 32 -> 16B aligned
        const bool full = (rh == WROWS);

        if (full) {
            if (lane == 0) {
                mbar_init(mbar, 1);
                fence_async();
                mbar_expect_tx(mbar, WBYTES);
                cp_bulk_ef(dst, xw, WBYTES, mbar);
            }
            __syncwarp();
        } else {
            const int total = rh * HW;
            const int n4 = total >> 2;
            const float4* xw4 = (const float4*)xw;
            for (int i = lane; i < n4; i += 32) cp16(dst + i * 16, xw4 + i);
            for (int i = 4 * n4 + lane; i < total; i += 32) cp4(dst + i * 4, xw + i);
            cp_commit();
        }

        // verify mask while copy flies: vectorized compare, 392 = 98 float4
        int mybad = 0;
        const float4* fm4 = (const float4*)fm;
        const float4* ex4 = (const float4*)g_exp;
        #pragma unroll
        for (int j = 0; j < 4; ++j) {
            int q = lane + j * 32;
            if (q < 98) {
                float4 v = __ldg(fm4 + q);
                float4 e = __ldg(ex4 + q);
                if (v.x != e.x || v.y != e.y || v.z != e.z || v.w != e.w) mybad = 1;
            }
        }
        const bool fb = __any_sync(0xffffffffu, mybad);

        if (full) mbar_wait(mbar, 0);
        else      { cp_wait_all(); __syncwarp(); }

        if (lane < rh) {
            const float* xr = wbuf + lane * HW;  // stride 49: conflict-free LDS
            float o[8];
            if (!fb) {
                const float x24 = xr[24];
                float R0 = xr[25] + xr[26] + xr[27];
                float R1 = xr[32] + xr[40] + xr[48];
                float R2 = xr[31] + xr[38] + xr[45];
                float R3 = xr[30] + xr[36] + xr[42];
                float R4 = xr[21] + xr[22] + xr[23];
                float R5 = xr[ 0] + xr[ 8] + xr[16];
                float R6 = xr[ 3] + xr[10] + xr[17];
                float R7 = xr[ 6] + xr[12] + xr[18];
                float I0 = xr[33] + xr[34] + xr[41];
                float I1 = xr[39] + xr[46] + xr[47];
                float I2 = xr[37] + xr[43] + xr[44];
                float I3 = xr[28] + xr[29] + xr[35];
                float I4 = xr[ 7] + xr[14] + xr[15];
                float I5 = xr[ 1] + xr[ 2] + xr[ 9];
                float I6 = xr[ 4] + xr[ 5] + xr[11];
                float I7 = xr[13] + xr[19] + xr[20];
                const float wgt = 0.1f;
                o[0] = (R0 + I0 + R1 + x24) * wgt;
                o[1] = (R1 + I1 + R2 + x24) * wgt;
                o[2] = (R2 + I2 + R3 + x24) * wgt;
                o[3] = (R3 + I3 + R4 + x24) * wgt;
                o[4] = (R4 + I4 + R5 + x24) * wgt;
                o[5] = (R5 + I5 + R6 + x24) * wgt;
                o[6] = (R6 + I6 + R7 + x24) * wgt;
                o[7] = (R7 + I7 + R0 + x24) * wgt;
            } else {
                // generic dense fallback (rare): read mask from gmem (cached)
                #pragma unroll
                for (int p = 0; p < 8; ++p) {
                    float acc = 0.0f, cnt = 0.0f;
                    for (int k = 0; k < HW; ++k) {
                        float m = __ldg(fm + p * HW + k);
                        acc += xr[k] * m;
                        cnt += (m != 0.0f) ? 1.0f : 0.0f;
                    }
                    o[p] = acc / cnt;
                }
            }
            float4* op = (float4*)(out + (wrow0 + lane) * 8);
            op[0] = make_float4(o[0], o[1], o[2], o[3]);
            op[1] = make_float4(o[4], o[5], o[6], o[7]);
        }
    } else {
        // ============ sal gather: direct (no smem), one block per batch ====
        const int b = blk;
        const float* sb = s + (long long)b * SROW;
        float* ob = out + feat_elems + (long long)b * (8LL * N);
        for (int n = t; n < N; n += TPB) {
            float v[8];
            #pragma unroll
            for (int p = 0; p < 8; ++p)
                v[p] = ldg_ef(sb + __ldg(sal_idx + p * N + n));
            float4* op = (float4*)(ob + n * 8);
            op[0] = make_float4(v[0], v[1], v[2], v[3]);
            op[1] = make_float4(v[4], v[5], v[6], v[7]);
        }
    }
}

extern "C" void kernel_launch(void* const* d_in, const int* in_sizes, int n_in,
                              void* d_out, int out_size) {
    const float* x       = (const float*)d_in[0];
    const float* s       = (const float*)d_in[1];
    const float* fm      = (const float*)d_in[2];
    const int*   sal_idx = (const int*)d_in[3];
    float*       out     = (float*)d_out;

    const int rows = in_sizes[0] / HW;    // B*C
    const int B    = in_sizes[1] / SROW;  // batch
    const int N    = in_sizes[3] / 8;     // points per direction
    const int nfb  = (rows + TPB - 1) / TPB;
    const long long feat_elems = (long long)rows * 8;

    fused_kernel<<<B + nfb, TPB>>>(x, s, fm, sal_idx, out, rows, B, N, feat_elems);
}

// round 17
// speedup vs baseline: 1.0977x; 1.0977x over previous
#include <cuda_runtime.h>
#include <cstdint>

// MultiDirectionPattern: masked 8-direction pooling + saliency gather.
// R15 CONFIGURATION (best measured total: 20.992us) — champion structure
// with L2::evict_first ONLY on the x-tile cp.async.bulk (x is strictly
// read-once). Sal gathers use plain __ldg (s has slight intra-batch reuse,
// and per-scalar policy regs hurt the 8-deep gather chain — R16 evidence).

static constexpr int HW    = 49;     // 7*7
static constexpr int TPB   = 64;
static constexpr int SROW  = 3136;   // 56*56
static constexpr int WROWS = 32;     // rows per warp
static constexpr int WF    = WROWS * HW;     // 1568 floats per warp slice
static constexpr int WBYTES = WF * 4;        // 6272 bytes
static constexpr int SM_FLOATS = 2 * WF;     // 3136 floats = 12544 B

// Expected mask values (1.0 where feat_mask[p][k] != 0): vectorized verify.
#define Z 0.f
#define O 1.f
__device__ const float g_exp[392] = {
// p0: 24,25,26,27,32,33,34,40,41,48
Z,Z,Z,Z,Z,Z,Z,Z,Z,Z,Z,Z,Z,Z,Z,Z,Z,Z,Z,Z,Z,Z,Z,Z,O,O,O,O,Z,Z,Z,Z,O,O,O,Z,Z,Z,Z,Z,O,O,Z,Z,Z,Z,Z,Z,O,
// p1: 24,31,32,38,39,40,45,46,47,48
Z,Z,Z,Z,Z,Z,Z,Z,Z,Z,Z,Z,Z,Z,Z,Z,Z,Z,Z,Z,Z,Z,Z,Z,O,Z,Z,Z,Z,Z,Z,O,O,Z,Z,Z,Z,Z,O,O,O,Z,Z,Z,Z,O,O,O,O,
// p2: 24,30,31,36,37,38,42,43,44,45
Z,Z,Z,Z,Z,Z,Z,Z,Z,Z,Z,Z,Z,Z,Z,Z,Z,Z,Z,Z,Z,Z,Z,Z,O,Z,Z,Z,Z,Z,O,O,Z,Z,Z,Z,O,O,O,Z,Z,Z,O,O,O,O,Z,Z,Z,
// p3: 21,22,23,24,28,29,30,35,36,42
Z,Z,Z,Z,Z,Z,Z,Z,Z,Z,Z,Z,Z,Z,Z,Z,Z,Z,Z,Z,Z,O,O,O,O,Z,Z,Z,O,O,O,Z,Z,Z,Z,O,O,Z,Z,Z,Z,Z,O,Z,Z,Z,Z,Z,Z,
// p4: 0,7,8,14,15,16,21,22,23,24
O,Z,Z,Z,Z,Z,Z,O,O,Z,Z,Z,Z,Z,O,O,O,Z,Z,Z,Z,O,O,O,O,Z,Z,Z,Z,Z,Z,Z,Z,Z,Z,Z,Z,Z,Z,Z,Z,Z,Z,Z,Z,Z,Z,Z,Z,
// p5: 0,1,2,3,8,9,10,16,17,24
O,O,O,O,Z,Z,Z,Z,O,O,O,Z,Z,Z,Z,Z,O,O,Z,Z,Z,Z,Z,Z,O,Z,Z,Z,Z,Z,Z,Z,Z,Z,Z,Z,Z,Z,Z,Z,Z,Z,Z,Z,Z,Z,Z,Z,Z,
// p6: 3,4,5,6,10,11,12,17,18,24
Z,Z,Z,O,O,O,O,Z,Z,Z,O,O,O,Z,Z,Z,Z,O,O,Z,Z,Z,Z,Z,O,Z,Z,Z,Z,Z,Z,Z,Z,Z,Z,Z,Z,Z,Z,Z,Z,Z,Z,Z,Z,Z,Z,Z,Z,
// p7: 6,12,13,18,19,20,24,25,26,27
Z,Z,Z,Z,Z,Z,O,Z,Z,Z,Z,Z,O,O,Z,Z,Z,Z,O,O,O,Z,Z,Z,O,O,O,O,Z,Z,Z,Z,Z,Z,Z,Z,Z,Z,Z,Z,Z,Z,Z,Z,Z,Z,Z,Z,Z
};
#undef Z
#undef O

__device__ __forceinline__ void cp16(uint32_t dst, const void* src) {
    asm volatile("cp.async.cg.shared.global [%0], [%1], 16;\n" :: "r"(dst), "l"(src));
}
__device__ __forceinline__ void cp4(uint32_t dst, const void* src) {
    asm volatile("cp.async.ca.shared.global [%0], [%1], 4;\n" :: "r"(dst), "l"(src));
}
__device__ __forceinline__ void cp_commit() {
    asm volatile("cp.async.commit_group;\n" ::: "memory");
}
__device__ __forceinline__ void cp_wait_all() {
    asm volatile("cp.async.wait_group 0;\n" ::: "memory");
}
__device__ __forceinline__ void mbar_init(uint32_t mbar, uint32_t cnt) {
    asm volatile("mbarrier.init.shared.b64 [%0], %1;\n" :: "r"(mbar), "r"(cnt) : "memory");
}
__device__ __forceinline__ void fence_async() {
    asm volatile("fence.proxy.async.shared::cta;\n" ::: "memory");
}
__device__ __forceinline__ void mbar_expect_tx(uint32_t mbar, uint32_t bytes) {
    asm volatile("mbarrier.arrive.expect_tx.shared.b64 _, [%0], %1;\n"
                 :: "r"(mbar), "r"(bytes) : "memory");
}
// bulk copy with L2 evict_first cache hint (x is read-once)
__device__ __forceinline__ void cp_bulk_ef(uint32_t dst, const void* src,
                                           uint32_t bytes, uint32_t mbar) {
    asm volatile(
        "{\n\t.reg .b64 pol;\n\t"
        "createpolicy.fractional.L2::evict_first.b64 pol, 1.0;\n\t"
        "cp.async.bulk.shared::cta.global.mbarrier::complete_tx::bytes.L2::cache_hint "
        "[%0], [%1], %2, [%3], pol;\n\t}"
        :: "r"(dst), "l"(src), "r"(bytes), "r"(mbar) : "memory");
}
__device__ __forceinline__ void mbar_wait(uint32_t mbar, uint32_t parity) {
    uint32_t done;
    asm volatile(
        "{\n\t.reg .pred p;\n\t"
        "mbarrier.try_wait.parity.acquire.cta.shared::cta.b64 p, [%1], %2;\n\t"
        "selp.b32 %0, 1, 0, p;\n\t}"
        : "=r"(done) : "r"(mbar), "r"(parity) : "memory");
    if (!done) {
        asm volatile(
            "{\n\t.reg .pred P1;\n\t"
            "WL_%=:\n\t"
            "mbarrier.try_wait.parity.acquire.cta.shared::cta.b64 P1, [%0], %1, 0x989680;\n\t"
            "@P1 bra.uni WD_%=;\n\t"
            "bra.uni WL_%=;\n\t"
            "WD_%=:\n\t}"
            :: "r"(mbar), "r"(parity) : "memory");
    }
}

__global__ __launch_bounds__(TPB, 17) void fused_kernel(
    const float* __restrict__ x,
    const float* __restrict__ s,
    const float* __restrict__ fm,
    const int*   __restrict__ sal_idx,
    float*       __restrict__ out,
    int rows,             // B*C
    int B,                // batch (sal blocks are blk < B)
    int N,                // saliency points per direction
    long long feat_elems  // rows*8
) {
    __shared__ __align__(16) float sm[SM_FLOATS];
    __shared__ __align__(8) unsigned long long smbar[2];
    const int blk = blockIdx.x;
    const int t   = threadIdx.x;

    if (blk >= B) {
        // ============ feat tile: warp-autonomous, 32 rows/warp ============
        const uint32_t sbase = (uint32_t)__cvta_generic_to_shared(sm);
        const uint32_t mbase = (uint32_t)__cvta_generic_to_shared(smbar);
        const int w    = t >> 5;
        const int lane = t & 31;
        const long long wrow0 = (long long)(blk - B) * TPB + (long long)w * WROWS;
        long long rem = rows - wrow0;
        if (rem <= 0) return;                    // no barriers in this path
        const int rh = rem < WROWS ? (int)rem : WROWS;

        float* wbuf = sm + w * WF;
        const uint32_t dst  = sbase + (uint32_t)w * WBYTES;
        const uint32_t mbar = mbase + (uint32_t)w * 8;
        const float* xw = x + wrow0 * HW;        // wrow0 mult of 32 -> 16B aligned
        const bool full = (rh == WROWS);

        if (full) {
            if (lane == 0) {
                mbar_init(mbar, 1);
                fence_async();
                mbar_expect_tx(mbar, WBYTES);
                cp_bulk_ef(dst, xw, WBYTES, mbar);
            }
            __syncwarp();
        } else {
            const int total = rh * HW;
            const int n4 = total >> 2;
            const float4* xw4 = (const float4*)xw;
            for (int i = lane; i < n4; i += 32) cp16(dst + i * 16, xw4 + i);
            for (int i = 4 * n4 + lane; i < total; i += 32) cp4(dst + i * 4, xw + i);
            cp_commit();
        }

        // verify mask while copy flies: vectorized compare, 392 = 98 float4
        int mybad = 0;
        const float4* fm4 = (const float4*)fm;
        const float4* ex4 = (const float4*)g_exp;
        #pragma unroll
        for (int j = 0; j < 4; ++j) {
            int q = lane + j * 32;
            if (q < 98) {
                float4 v = __ldg(fm4 + q);
                float4 e = __ldg(ex4 + q);
                if (v.x != e.x || v.y != e.y || v.z != e.z || v.w != e.w) mybad = 1;
            }
        }
        const bool fb = __any_sync(0xffffffffu, mybad);

        if (full) mbar_wait(mbar, 0);
        else      { cp_wait_all(); __syncwarp(); }

        if (lane < rh) {
            const float* xr = wbuf + lane * HW;  // stride 49: conflict-free LDS
            float o[8];
            if (!fb) {
                const float x24 = xr[24];
                float R0 = xr[25] + xr[26] + xr[27];
                float R1 = xr[32] + xr[40] + xr[48];
                float R2 = xr[31] + xr[38] + xr[45];
                float R3 = xr[30] + xr[36] + xr[42];
                float R4 = xr[21] + xr[22] + xr[23];
                float R5 = xr[ 0] + xr[ 8] + xr[16];
                float R6 = xr[ 3] + xr[10] + xr[17];
                float R7 = xr[ 6] + xr[12] + xr[18];
                float I0 = xr[33] + xr[34] + xr[41];
                float I1 = xr[39] + xr[46] + xr[47];
                float I2 = xr[37] + xr[43] + xr[44];
                float I3 = xr[28] + xr[29] + xr[35];
                float I4 = xr[ 7] + xr[14] + xr[15];
                float I5 = xr[ 1] + xr[ 2] + xr[ 9];
                float I6 = xr[ 4] + xr[ 5] + xr[11];
                float I7 = xr[13] + xr[19] + xr[20];
                const float wgt = 0.1f;
                o[0] = (R0 + I0 + R1 + x24) * wgt;
                o[1] = (R1 + I1 + R2 + x24) * wgt;
                o[2] = (R2 + I2 + R3 + x24) * wgt;
                o[3] = (R3 + I3 + R4 + x24) * wgt;
                o[4] = (R4 + I4 + R5 + x24) * wgt;
                o[5] = (R5 + I5 + R6 + x24) * wgt;
                o[6] = (R6 + I6 + R7 + x24) * wgt;
                o[7] = (R7 + I7 + R0 + x24) * wgt;
            } else {
                // generic dense fallback (rare): read mask from gmem (cached)
                #pragma unroll
                for (int p = 0; p < 8; ++p) {
                    float acc = 0.0f, cnt = 0.0f;
                    for (int k = 0; k < HW; ++k) {
                        float m = __ldg(fm + p * HW + k);
                        acc += xr[k] * m;
                        cnt += (m != 0.0f) ? 1.0f : 0.0f;
                    }
                    o[p] = acc / cnt;
                }
            }
            float4* op = (float4*)(out + (wrow0 + lane) * 8);
            op[0] = make_float4(o[0], o[1], o[2], o[3]);
            op[1] = make_float4(o[4], o[5], o[6], o[7]);
        }
    } else {
        // ============ sal gather: direct (no smem), one block per batch ====
        const int b = blk;
        const float* sb = s + (long long)b * SROW;
        float* ob = out + feat_elems + (long long)b * (8LL * N);
        for (int n = t; n < N; n += TPB) {
            float v[8];
            #pragma unroll
            for (int p = 0; p < 8; ++p)
                v[p] = __ldg(sb + __ldg(sal_idx + p * N + n));
            float4* op = (float4*)(ob + n * 8);
            op[0] = make_float4(v[0], v[1], v[2], v[3]);
            op[1] = make_float4(v[4], v[5], v[6], v[7]);
        }
    }
}

extern "C" void kernel_launch(void* const* d_in, const int* in_sizes, int n_in,
                              void* d_out, int out_size) {
    const float* x       = (const float*)d_in[0];
    const float* s       = (const float*)d_in[1];
    const float* fm      = (const float*)d_in[2];
    const int*   sal_idx = (const int*)d_in[3];
    float*       out     = (float*)d_out;

    const int rows = in_sizes[0] / HW;    // B*C
    const int B    = in_sizes[1] / SROW;  // batch
    const int N    = in_sizes[3] / 8;     // points per direction
    const int nfb  = (rows + TPB - 1) / TPB;
    const long long feat_elems = (long long)rows * 8;

    fused_kernel<<<B + nfb, TPB>>>(x, s, fm, sal_idx, out, rows, B, N, feat_elems);
}